// round 6
// baseline (speedup 1.0000x reference)
#include <cuda_runtime.h>
#include <cuda_bf16.h>
#include <cstdint>

// Inputs (metadata order):
//   0: x          float32 [200000]
//   1: Param_W    float32 [1000000]
//   2: Param_b    float32 [500]
//   3: src        int32   [12800000]
//   4: dst        int32   [12800000]
//   5: weight_idx int32   [12800000]
//   6: node_label int32   [200000]
// Output: y float32 [200000]

__global__ void init_bias_kernel(const float* __restrict__ Param_b,
                                 const int* __restrict__ node_label,
                                 float* __restrict__ y,
                                 int n_nodes) {
    int i = blockIdx.x * blockDim.x + threadIdx.x;
    if (i < n_nodes) {
        y[i] = __ldg(&Param_b[node_label[i]]);
    }
}

// Persistent edge kernel: grid sized to exactly fill the chip (148 SMs x 8 CTAs).
// Each thread grid-strides over int4 groups (4 edges/iter). The loop is
// software-pipelined: next iteration's 3 stream loads are issued before this
// iteration's atomics, so the per-SM L1tex queue never drains and there are
// no wave transitions (single persistent wave).
__global__ void __launch_bounds__(256, 8)
edge_scatter_persist_kernel(const float* __restrict__ x,
                            const float* __restrict__ Param_W,
                            const int4* __restrict__ src4,
                            const int4* __restrict__ dst4,
                            const int4* __restrict__ wi4,
                            float* __restrict__ y,
                            int n_vec) {
    int i = blockIdx.x * blockDim.x + threadIdx.x;
    const int stride = gridDim.x * blockDim.x;

    if (i >= n_vec) return;

    // Prologue: first iteration's stream loads
    int4 s = __ldcs(&src4[i]);
    int4 w = __ldcs(&wi4[i]);
    int4 d = __ldcs(&dst4[i]);

    for (;;) {
        int inext = i + stride;
        bool more = inext < n_vec;

        // Random gathers for current iteration (8 independent loads in flight)
        float w0 = __ldcg(&Param_W[w.x]);
        float w1 = __ldcg(&Param_W[w.y]);
        float w2 = __ldcg(&Param_W[w.z]);
        float w3 = __ldcg(&Param_W[w.w]);
        float x0 = x[s.x];
        float x1 = x[s.y];
        float x2 = x[s.z];
        float x3 = x[s.w];

        // Prefetch next iteration's stream loads before the atomics
        int4 sn, wn, dn;
        if (more) {
            sn = __ldcs(&src4[inext]);
            wn = __ldcs(&wi4[inext]);
            dn = __ldcs(&dst4[inext]);
        }

        atomicAdd(&y[d.x], w0 * x0);
        atomicAdd(&y[d.y], w1 * x1);
        atomicAdd(&y[d.z], w2 * x2);
        atomicAdd(&y[d.w], w3 * x3);

        if (!more) break;
        i = inext;
        s = sn; w = wn; d = dn;
    }
}

// Scalar tail for edge counts not divisible by 4 (not hit for 12.8M).
__global__ void edge_scatter_tail_kernel(const float* __restrict__ x,
                                         const float* __restrict__ Param_W,
                                         const int* __restrict__ src,
                                         const int* __restrict__ dst,
                                         const int* __restrict__ wi,
                                         float* __restrict__ y,
                                         int start, int n_edges) {
    int i = start + blockIdx.x * blockDim.x + threadIdx.x;
    if (i < n_edges) {
        float m = __ldcg(&Param_W[wi[i]]) * x[src[i]];
        atomicAdd(&y[dst[i]], m);
    }
}

extern "C" void kernel_launch(void* const* d_in, const int* in_sizes, int n_in,
                              void* d_out, int out_size) {
    const float* x          = (const float*)d_in[0];
    const float* Param_W    = (const float*)d_in[1];
    const float* Param_b    = (const float*)d_in[2];
    const int*   src        = (const int*)d_in[3];
    const int*   dst        = (const int*)d_in[4];
    const int*   weight_idx = (const int*)d_in[5];
    const int*   node_label = (const int*)d_in[6];
    float* y = (float*)d_out;

    int n_nodes = in_sizes[0];
    int n_edges = in_sizes[3];

    // 1) y = Param_b[node_label]
    {
        int threads = 256;
        int blocks = (n_nodes + threads - 1) / threads;
        init_bias_kernel<<<blocks, threads>>>(Param_b, node_label, y, n_nodes);
    }

    // 2) scatter-add messages: persistent grid, 4 edges/thread/iter
    int n_vec = n_edges / 4;
    if (n_vec > 0) {
        const int threads = 256;
        // 152 SMs on GB300; use 152*8 CTAs to fill the chip in one wave.
        int blocks = 152 * 8;
        long long need = ((long long)n_vec + threads - 1) / threads;
        if ((long long)blocks > need) blocks = (int)need;
        edge_scatter_persist_kernel<<<blocks, threads>>>(
            x, Param_W,
            (const int4*)src, (const int4*)dst, (const int4*)weight_idx,
            y, n_vec);
    }
    int tail_start = n_vec * 4;
    int tail = n_edges - tail_start;
    if (tail > 0) {
        int threads = 256;
        int blocks = (tail + threads - 1) / threads;
        edge_scatter_tail_kernel<<<blocks, threads>>>(
            x, Param_W, src, dst, weight_idx, y, tail_start, n_edges);
    }
}

// round 7
// speedup vs baseline: 1.4868x; 1.4868x over previous
#include <cuda_runtime.h>
#include <cuda_bf16.h>
#include <cstdint>

// Inputs (metadata order):
//   0: x          float32 [200000]
//   1: Param_W    float32 [1000000]
//   2: Param_b    float32 [500]
//   3: src        int32   [12800000]
//   4: dst        int32   [12800000]
//   5: weight_idx int32   [12800000]
//   6: node_label int32   [200000]
// Output: y float32 [200000]

// Vectorized bias init: 4 nodes per thread (int4 label load, float4 y store).
__global__ void init_bias_vec4_kernel(const float* __restrict__ Param_b,
                                      const int4* __restrict__ node_label4,
                                      float4* __restrict__ y4,
                                      int n_vec) {
    int i = blockIdx.x * blockDim.x + threadIdx.x;
    if (i < n_vec) {
        int4 l = node_label4[i];
        float4 v;
        v.x = __ldg(&Param_b[l.x]);
        v.y = __ldg(&Param_b[l.y]);
        v.z = __ldg(&Param_b[l.z]);
        v.w = __ldg(&Param_b[l.w]);
        y4[i] = v;
    }
}

__global__ void init_bias_tail_kernel(const float* __restrict__ Param_b,
                                      const int* __restrict__ node_label,
                                      float* __restrict__ y,
                                      int start, int n_nodes) {
    int i = start + blockIdx.x * blockDim.x + threadIdx.x;
    if (i < n_nodes) {
        y[i] = __ldg(&Param_b[node_label[i]]);
    }
}

// Edge kernel (best measured shape, R2): one-shot grid, 4 edges/thread via
// int4 loads, default cache policy everywhere (lets hot Param_W / x lines
// earn L1 hits), RED.E.ADD scatter.
__global__ void __launch_bounds__(256, 8)
edge_scatter_vec4_kernel(const float* __restrict__ x,
                         const float* __restrict__ Param_W,
                         const int4* __restrict__ src4,
                         const int4* __restrict__ dst4,
                         const int4* __restrict__ wi4,
                         float* __restrict__ y,
                         int n_vec) {
    int i = blockIdx.x * blockDim.x + threadIdx.x;
    int stride = gridDim.x * blockDim.x;
    for (; i < n_vec; i += stride) {
        int4 s = src4[i];
        int4 d = dst4[i];
        int4 w = wi4[i];

        float m0 = __ldg(&Param_W[w.x]) * __ldg(&x[s.x]);
        float m1 = __ldg(&Param_W[w.y]) * __ldg(&x[s.y]);
        float m2 = __ldg(&Param_W[w.z]) * __ldg(&x[s.z]);
        float m3 = __ldg(&Param_W[w.w]) * __ldg(&x[s.w]);

        atomicAdd(&y[d.x], m0);
        atomicAdd(&y[d.y], m1);
        atomicAdd(&y[d.z], m2);
        atomicAdd(&y[d.w], m3);
    }
}

// Scalar tail for edge counts not divisible by 4 (not hit for 12.8M).
__global__ void edge_scatter_tail_kernel(const float* __restrict__ x,
                                         const float* __restrict__ Param_W,
                                         const int* __restrict__ src,
                                         const int* __restrict__ dst,
                                         const int* __restrict__ wi,
                                         float* __restrict__ y,
                                         int start, int n_edges) {
    int i = start + blockIdx.x * blockDim.x + threadIdx.x;
    if (i < n_edges) {
        float m = __ldg(&Param_W[wi[i]]) * __ldg(&x[src[i]]);
        atomicAdd(&y[dst[i]], m);
    }
}

extern "C" void kernel_launch(void* const* d_in, const int* in_sizes, int n_in,
                              void* d_out, int out_size) {
    const float* x          = (const float*)d_in[0];
    const float* Param_W    = (const float*)d_in[1];
    const float* Param_b    = (const float*)d_in[2];
    const int*   src        = (const int*)d_in[3];
    const int*   dst        = (const int*)d_in[4];
    const int*   weight_idx = (const int*)d_in[5];
    const int*   node_label = (const int*)d_in[6];
    float* y = (float*)d_out;

    int n_nodes = in_sizes[0];
    int n_edges = in_sizes[3];

    // 1) y = Param_b[node_label]  (vectorized 4 nodes/thread)
    {
        int n_nvec = n_nodes / 4;
        if (n_nvec > 0) {
            int threads = 256;
            int blocks = (n_nvec + threads - 1) / threads;
            init_bias_vec4_kernel<<<blocks, threads>>>(
                Param_b, (const int4*)node_label, (float4*)y, n_nvec);
        }
        int tstart = n_nvec * 4;
        int trem = n_nodes - tstart;
        if (trem > 0) {
            int threads = 256;
            int blocks = (trem + threads - 1) / threads;
            init_bias_tail_kernel<<<blocks, threads>>>(
                Param_b, node_label, y, tstart, n_nodes);
        }
    }

    // 2) scatter-add messages: one-shot grid, 4 edges/thread
    int n_vec = n_edges / 4;
    if (n_vec > 0) {
        int threads = 256;
        long long want = ((long long)n_vec + threads - 1) / threads;
        long long cap = 65535LL * 1024LL;
        int blocks = (int)(want > cap ? cap : want);
        edge_scatter_vec4_kernel<<<blocks, threads>>>(
            x, Param_W,
            (const int4*)src, (const int4*)dst, (const int4*)weight_idx,
            y, n_vec);
    }
    int tail_start = n_vec * 4;
    int tail = n_edges - tail_start;
    if (tail > 0) {
        int threads = 256;
        int blocks = (tail + threads - 1) / threads;
        edge_scatter_tail_kernel<<<blocks, threads>>>(
            x, Param_W, src, dst, weight_idx, y, tail_start, n_edges);
    }
}

// round 8
// speedup vs baseline: 1.5200x; 1.0223x over previous
#include <cuda_runtime.h>
#include <cuda_bf16.h>
#include <cstdint>

// Inputs (metadata order):
//   0: x          float32 [200000]
//   1: Param_W    float32 [1000000]
//   2: Param_b    float32 [500]
//   3: src        int32   [12800000]
//   4: dst        int32   [12800000]
//   5: weight_idx int32   [12800000]
//   6: node_label int32   [200000]
// Output: y float32 [200000]

// Vectorized bias init: 4 nodes per thread (int4 label load, float4 y store).
// No explicit PDL trigger: implicit trigger at kernel completion guarantees
// all y stores are visible to the dependent grid after gridDepSync.
__global__ void init_bias_vec4_kernel(const float* __restrict__ Param_b,
                                      const int4* __restrict__ node_label4,
                                      float4* __restrict__ y4,
                                      int n_vec) {
    int i = blockIdx.x * blockDim.x + threadIdx.x;
    if (i < n_vec) {
        int4 l = node_label4[i];
        float4 v;
        v.x = __ldg(&Param_b[l.x]);
        v.y = __ldg(&Param_b[l.y]);
        v.z = __ldg(&Param_b[l.z]);
        v.w = __ldg(&Param_b[l.w]);
        y4[i] = v;
    }
}

__global__ void init_bias_tail_kernel(const float* __restrict__ Param_b,
                                      const int* __restrict__ node_label,
                                      float* __restrict__ y,
                                      int start, int n_nodes) {
    int i = start + blockIdx.x * blockDim.x + threadIdx.x;
    if (i < n_nodes) {
        y[i] = __ldg(&Param_b[node_label[i]]);
    }
}

// Edge kernel (floor shape: one-shot grid, 4 edges/thread, default cache
// policy, RED.E.ADD scatter) launched with PDL. Each thread issues all its
// loads and products FIRST (independent of y), then waits for the init
// kernel via cudaGridDependencySynchronize() exactly once before its first
// atomic. The load latency overlaps the init kernel's execution.
__global__ void __launch_bounds__(256, 8)
edge_scatter_vec4_pdl_kernel(const float* __restrict__ x,
                             const float* __restrict__ Param_W,
                             const int4* __restrict__ src4,
                             const int4* __restrict__ dst4,
                             const int4* __restrict__ wi4,
                             float* __restrict__ y,
                             int n_vec) {
    int i = blockIdx.x * blockDim.x + threadIdx.x;
    int stride = gridDim.x * blockDim.x;
    bool synced = false;

    for (; i < n_vec; i += stride) {
        int4 s = src4[i];
        int4 d = dst4[i];
        int4 w = wi4[i];

        float m0 = __ldg(&Param_W[w.x]) * __ldg(&x[s.x]);
        float m1 = __ldg(&Param_W[w.y]) * __ldg(&x[s.y]);
        float m2 = __ldg(&Param_W[w.z]) * __ldg(&x[s.z]);
        float m3 = __ldg(&Param_W[w.w]) * __ldg(&x[s.w]);

        if (!synced) {
#if __CUDA_ARCH__ >= 900
            cudaGridDependencySynchronize();
#endif
            synced = true;
        }

        atomicAdd(&y[d.x], m0);
        atomicAdd(&y[d.y], m1);
        atomicAdd(&y[d.z], m2);
        atomicAdd(&y[d.w], m3);
    }
}

// Scalar tail for edge counts not divisible by 4 (not hit for 12.8M).
__global__ void edge_scatter_tail_kernel(const float* __restrict__ x,
                                         const float* __restrict__ Param_W,
                                         const int* __restrict__ src,
                                         const int* __restrict__ dst,
                                         const int* __restrict__ wi,
                                         float* __restrict__ y,
                                         int start, int n_edges) {
    int i = start + blockIdx.x * blockDim.x + threadIdx.x;
    if (i < n_edges) {
        float m = __ldg(&Param_W[wi[i]]) * __ldg(&x[src[i]]);
        atomicAdd(&y[dst[i]], m);
    }
}

extern "C" void kernel_launch(void* const* d_in, const int* in_sizes, int n_in,
                              void* d_out, int out_size) {
    const float* x          = (const float*)d_in[0];
    const float* Param_W    = (const float*)d_in[1];
    const float* Param_b    = (const float*)d_in[2];
    const int*   src        = (const int*)d_in[3];
    const int*   dst        = (const int*)d_in[4];
    const int*   weight_idx = (const int*)d_in[5];
    const int*   node_label = (const int*)d_in[6];
    float* y = (float*)d_out;

    int n_nodes = in_sizes[0];
    int n_edges = in_sizes[3];

    // 1) y = Param_b[node_label]  (vectorized 4 nodes/thread)
    {
        int n_nvec = n_nodes / 4;
        if (n_nvec > 0) {
            int threads = 256;
            int blocks = (n_nvec + threads - 1) / threads;
            init_bias_vec4_kernel<<<blocks, threads>>>(
                Param_b, (const int4*)node_label, (float4*)y, n_nvec);
        }
        int tstart = n_nvec * 4;
        int trem = n_nodes - tstart;
        if (trem > 0) {
            int threads = 256;
            int blocks = (trem + threads - 1) / threads;
            init_bias_tail_kernel<<<blocks, threads>>>(
                Param_b, node_label, y, tstart, n_nodes);
        }
    }

    // 2) scatter-add messages: one-shot grid, 4 edges/thread, launched with
    //    Programmatic Dependent Launch so its load phase overlaps the init
    //    kernel. Falls back to a plain launch if PDL setup fails.
    int n_vec = n_edges / 4;
    if (n_vec > 0) {
        const int threads = 256;
        long long want = ((long long)n_vec + threads - 1) / threads;
        long long cap = 65535LL * 1024LL;
        int blocks = (int)(want > cap ? cap : want);

        cudaLaunchConfig_t cfg = {};
        cfg.gridDim = dim3((unsigned)blocks, 1, 1);
        cfg.blockDim = dim3(threads, 1, 1);
        cfg.dynamicSmemBytes = 0;
        cfg.stream = 0;

        cudaLaunchAttribute attrs[1];
        attrs[0].id = cudaLaunchAttributeProgrammaticStreamSerialization;
        attrs[0].val.programmaticStreamSerializationAllowed = 1;
        cfg.attrs = attrs;
        cfg.numAttrs = 1;

        cudaError_t e = cudaLaunchKernelEx(&cfg, edge_scatter_vec4_pdl_kernel,
                                           x, Param_W,
                                           (const int4*)src, (const int4*)dst,
                                           (const int4*)weight_idx,
                                           y, n_vec);
        if (e != cudaSuccess) {
            // Fallback: plain launch (gridDepSync degrades to no-op ordering)
            edge_scatter_vec4_pdl_kernel<<<blocks, threads>>>(
                x, Param_W,
                (const int4*)src, (const int4*)dst, (const int4*)weight_idx,
                y, n_vec);
        }
    }
    int tail_start = n_vec * 4;
    int tail = n_edges - tail_start;
    if (tail > 0) {
        int threads = 256;
        int blocks = (tail + threads - 1) / threads;
        edge_scatter_tail_kernel<<<blocks, threads>>>(
            x, Param_W, src, dst, weight_idx, y, tail_start, n_edges);
    }
}